// round 2
// baseline (speedup 1.0000x reference)
#include <cuda_runtime.h>
#include <cstdint>

#define BB    256
#define TT    256
#define DD    128
#define HH    384
#define LL    12
#define GG    1560
#define KTOT  512
#define NPAD  1776
#define GRIDC 148
#define MT    64
#define NT    48
#define KC    16
#define NCHUNK (KTOT / KC)
#define FULLMASK 0xffffffffu

__device__ __align__(16) float g_Wc[KTOT * NPAD];
__device__ __align__(16) float g_wt[NPAD];
__device__ __align__(16) float g_bias[NPAD];
__device__ __align__(16) float g_xT[TT * BB * DD];
__device__ __align__(16) float g_h[BB * HH];
__device__ __align__(16) float g_c[BB * HH];
__device__ __align__(16) float g_xout[BB * NPAD];
__device__ unsigned g_bar_arrive;
__device__ volatile unsigned g_bar_release;

#define FFMA2(acc, a, b) \
    asm("fma.rn.f32x2 %0, %1, %2, %0;" : "+l"(acc) : "l"(a), "l"(b))
#define UNPK(v, lo, hi) \
    asm("mov.b64 {%0, %1}, %2;" : "=f"(lo), "=f"(hi) : "l"(v))

__device__ __forceinline__ float fsig(float x) { return 1.0f / (1.0f + __expf(-x)); }
__device__ __forceinline__ float ftanh(float x) {
    float a = __expf(-2.0f * fabsf(x));
    return copysignf((1.0f - a) / (1.0f + a), x);
}
__device__ __forceinline__ float warpMax(float v) {
    #pragma unroll
    for (int o = 16; o > 0; o >>= 1) v = fmaxf(v, __shfl_xor_sync(FULLMASK, v, o));
    return v;
}
__device__ __forceinline__ float warpSum(float v) {
    #pragma unroll
    for (int o = 16; o > 0; o >>= 1) v += __shfl_xor_sync(FULLMASK, v, o);
    return v;
}

__device__ __forceinline__ void grid_barrier(unsigned gen) {
    __threadfence();
    __syncthreads();
    if (threadIdx.x == 0) {
        unsigned prev = atomicAdd(&g_bar_arrive, 1u);
        if (prev == gen * GRIDC - 1u) {
            g_bar_release = gen;
            __threadfence();
        } else {
            while (g_bar_release < gen) { }
            __threadfence();
        }
    }
    __syncthreads();
}

__global__ void prep_kernel(const float* __restrict__ x,
                            const float* __restrict__ Wk,
                            const float* __restrict__ bk,
                            const float* __restrict__ Wr,
                            const float* __restrict__ br) {
    int i = blockIdx.x * blockDim.x + threadIdx.x;
    int stride = gridDim.x * blockDim.x;
    if (i == 0) { g_bar_arrive = 0u; g_bar_release = 0u; }
    for (int j = i; j < BB * HH; j += stride) { g_h[j] = 0.f; g_c[j] = 0.f; }
    for (int j = i; j < KTOT * NPAD; j += stride) {
        int k = j / NPAD, n = j - k * NPAD;
        float v = 0.f;
        if (n < GG) v = (k < DD) ? Wk[k * GG + n] : Wr[(k - DD) * GG + n];
        g_Wc[j] = v;
    }
    for (int n = i; n < NPAD; n += stride) {
        g_wt[n]   = (n < GG) ? (Wk[DD * GG + n] + Wr[HH * GG + n]) : 0.f;
        g_bias[n] = (n < GG) ? (bk[n] + br[n]) : 0.f;
    }
    for (int j = i; j < BB * TT * DD; j += stride) {
        int d = j & (DD - 1);
        int t = (j / DD) & (TT - 1);
        int b = j / (DD * TT);
        g_xT[(t * BB + b) * DD + d] = x[j];
    }
}

__global__ void __launch_bounds__(256, 1)
scan_kernel(const float* __restrict__ time, float* __restrict__ out) {
    __shared__ __align__(16) float  As[2][KC][MT + 4];
    __shared__ __align__(16) float2 Bs[2][KC][NT];
    __shared__ float s_fm[LL], s_im[LL];

    const int tid  = threadIdx.x;
    const int cta  = blockIdx.x;
    const int m0 = (cta & 3) * MT;
    const int n0 = (cta >> 2) * NT;

    const int tm = tid & 15;
    const int tn = tid >> 4;
    const int arow = tid >> 2;
    const int aq   = tid & 3;
    const int brow = tid / 12;
    const int bq   = tid - brow * 12;

    const int bstart = (cta * BB) / GRIDC;
    const int bend   = ((cta + 1) * BB) / GRIDC;

    unsigned gen = 0;

    for (int t = 0; t < TT; ++t) {
        unsigned long long a00 = 0ull, a01 = 0ull, a02 = 0ull;
        unsigned long long a10 = 0ull, a11 = 0ull, a12 = 0ull;

        float4 aPf, bPf;
        aPf = *reinterpret_cast<const float4*>(
            g_xT + ((size_t)t * BB + (m0 + arow)) * DD + 4 * aq);
        if (tid < 192)
            bPf = *reinterpret_cast<const float4*>(
                g_Wc + (size_t)brow * NPAD + n0 + 4 * bq);

        As[0][4 * aq + 0][arow] = aPf.x;
        As[0][4 * aq + 1][arow] = aPf.y;
        As[0][4 * aq + 2][arow] = aPf.z;
        As[0][4 * aq + 3][arow] = aPf.w;
        if (tid < 192) {
            Bs[0][brow][4 * bq + 0] = make_float2(bPf.x, bPf.x);
            Bs[0][brow][4 * bq + 1] = make_float2(bPf.y, bPf.y);
            Bs[0][brow][4 * bq + 2] = make_float2(bPf.z, bPf.z);
            Bs[0][brow][4 * bq + 3] = make_float2(bPf.w, bPf.w);
        }

        for (int kc = 0; kc < NCHUNK; ++kc) {
            __syncthreads();
            const int buf = kc & 1;
            if (kc + 1 < NCHUNK) {
                int k = (kc + 1) * KC + 4 * aq;
                if (k < DD) {
                    aPf = *reinterpret_cast<const float4*>(
                        g_xT + ((size_t)t * BB + (m0 + arow)) * DD + k);
                } else {
                    aPf = __ldcg(reinterpret_cast<const float4*>(
                        g_h + (m0 + arow) * HH + (k - DD)));
                }
                if (tid < 192)
                    bPf = *reinterpret_cast<const float4*>(
                        g_Wc + (size_t)((kc + 1) * KC + brow) * NPAD + n0 + 4 * bq);
            }
            #pragma unroll
            for (int kk = 0; kk < KC; ++kk) {
                ulonglong2 aa = *reinterpret_cast<const ulonglong2*>(&As[buf][kk][4 * tm]);
                unsigned long long b0 = *reinterpret_cast<const unsigned long long*>(&Bs[buf][kk][3 * tn + 0]);
                unsigned long long b1 = *reinterpret_cast<const unsigned long long*>(&Bs[buf][kk][3 * tn + 1]);
                unsigned long long b2 = *reinterpret_cast<const unsigned long long*>(&Bs[buf][kk][3 * tn + 2]);
                FFMA2(a00, aa.x, b0); FFMA2(a10, aa.y, b0);
                FFMA2(a01, aa.x, b1); FFMA2(a11, aa.y, b1);
                FFMA2(a02, aa.x, b2); FFMA2(a12, aa.y, b2);
            }
            if (kc + 1 < NCHUNK) {
                const int nb = buf ^ 1;
                As[nb][4 * aq + 0][arow] = aPf.x;
                As[nb][4 * aq + 1][arow] = aPf.y;
                As[nb][4 * aq + 2][arow] = aPf.z;
                As[nb][4 * aq + 3][arow] = aPf.w;
                if (tid < 192) {
                    Bs[nb][brow][4 * bq + 0] = make_float2(bPf.x, bPf.x);
                    Bs[nb][brow][4 * bq + 1] = make_float2(bPf.y, bPf.y);
                    Bs[nb][brow][4 * bq + 2] = make_float2(bPf.z, bPf.z);
                    Bs[nb][brow][4 * bq + 3] = make_float2(bPf.w, bPf.w);
                }
            }
        }

        {
            const int r0 = m0 + 4 * tm;
            const int c0 = n0 + 3 * tn;
            float tr0 = time[(r0 + 0) * TT + t];
            float tr1 = time[(r0 + 1) * TT + t];
            float tr2 = time[(r0 + 2) * TT + t];
            float tr3 = time[(r0 + 3) * TT + t];
            float w0 = g_wt[c0 + 0], w1 = g_wt[c0 + 1], w2 = g_wt[c0 + 2];
            float e0 = g_bias[c0 + 0], e1 = g_bias[c0 + 1], e2 = g_bias[c0 + 2];
            float lo, hi;
            UNPK(a00, lo, hi);
            g_xout[(r0 + 0) * NPAD + c0 + 0] = lo + tr0 * w0 + e0;
            g_xout[(r0 + 1) * NPAD + c0 + 0] = hi + tr1 * w0 + e0;
            UNPK(a10, lo, hi);
            g_xout[(r0 + 2) * NPAD + c0 + 0] = lo + tr2 * w0 + e0;
            g_xout[(r0 + 3) * NPAD + c0 + 0] = hi + tr3 * w0 + e0;
            UNPK(a01, lo, hi);
            g_xout[(r0 + 0) * NPAD + c0 + 1] = lo + tr0 * w1 + e1;
            g_xout[(r0 + 1) * NPAD + c0 + 1] = hi + tr1 * w1 + e1;
            UNPK(a11, lo, hi);
            g_xout[(r0 + 2) * NPAD + c0 + 1] = lo + tr2 * w1 + e1;
            g_xout[(r0 + 3) * NPAD + c0 + 1] = hi + tr3 * w1 + e1;
            UNPK(a02, lo, hi);
            g_xout[(r0 + 0) * NPAD + c0 + 2] = lo + tr0 * w2 + e2;
            g_xout[(r0 + 1) * NPAD + c0 + 2] = hi + tr1 * w2 + e2;
            UNPK(a12, lo, hi);
            g_xout[(r0 + 2) * NPAD + c0 + 2] = lo + tr2 * w2 + e2;
            g_xout[(r0 + 3) * NPAD + c0 + 2] = hi + tr3 * w2 + e2;
        }

        grid_barrier(++gen);

        for (int b = bstart; b < bend; ++b) {
            const float* xr = g_xout + (size_t)b * NPAD;
            if (tid < 32) {
                int l = tid;
                float z1 = (l < LL) ? __ldcg(xr + l)      : -3.0e38f;
                float z2 = (l < LL) ? __ldcg(xr + LL + l) : -3.0e38f;
                float m1 = warpMax(z1), m2 = warpMax(z2);
                float p1 = (l < LL) ? __expf(z1 - m1) : 0.f;
                float p2 = (l < LL) ? __expf(z2 - m2) : 0.f;
                float s1 = warpSum(p1), s2 = warpSum(p2);
                p1 /= s1; p2 /= s2;
                float q1 = p1, q2 = p2;
                #pragma unroll
                for (int o = 1; o < 16; o <<= 1) {
                    float u1 = __shfl_up_sync(FULLMASK, q1, o);
                    float u2 = __shfl_up_sync(FULLMASK, q2, o);
                    if (l >= o) { q1 += u1; q2 += u2; }
                }
                if (l < LL) {
                    s_fm[l] = q1;                    // inclusive prefix (l2r cumax)
                    s_im[l] = 1.0f - (q2 - p2);      // inclusive suffix (r2l cumax)
                }
            }
            __syncthreads();
            const float* gr = xr + 2 * LL;
            for (int e = tid; e < HH; e += 256) {
                float f  = fsig(__ldcg(gr + e));
                float ig = fsig(__ldcg(gr + HH + e));
                float o  = fsig(__ldcg(gr + 2 * HH + e));
                float ci = ftanh(__ldcg(gr + 3 * HH + e));
                int   l  = e >> 5;
                float fm = s_fm[l], im = s_im[l];
                float ov = fm * im;
                float cl = g_c[b * HH + e];
                float cn = ov * (f * cl + ig * ci) + (fm - ov) * cl + (im - ov) * ci;
                float hn = o * ftanh(cn);
                g_c[b * HH + e] = cn;
                g_h[b * HH + e] = hn;
                out[((size_t)b * TT + t) * HH + e] = hn;
            }
            __syncthreads();
        }

        grid_barrier(++gen);
    }
}

extern "C" void kernel_launch(void* const* d_in, const int* in_sizes, int n_in,
                              void* d_out, int out_size) {
    const float* x    = (const float*)d_in[0];
    const float* time = (const float*)d_in[1];
    const float* Wk   = (const float*)d_in[2];
    const float* bk   = (const float*)d_in[3];
    const float* Wr   = (const float*)d_in[4];
    const float* br   = (const float*)d_in[5];
    float* out = (float*)d_out;
    prep_kernel<<<512, 256>>>(x, Wk, bk, Wr, br);
    scan_kernel<<<GRIDC, 256>>>(time, out);
}